// round 8
// baseline (speedup 1.0000x reference)
#include <cuda_runtime.h>
#include <cuda_bf16.h>
#include <math.h>

#define NN 50000
#define EE 800000
#define ETOT (EE + NN)   // edges + self loops = 850000
#define D 64
#define HH 4
#define CC 16
#define LL 3
#define FF 8
#define TEE 16

// ---------------- scratch (device globals; no allocs allowed) ----------------
__device__ float g_h[NN * D];
__device__ float g_h0[NN * D];
__device__ float g_xl[NN * D];
__device__ float g_xr[NN * D];
__device__ float g_xres[NN * D];
__device__ int   g_deg[NN];
__device__ int   g_rowptr[NN + 1];
__device__ int   g_cursor[NN];
__device__ int   g_col[ETOT];
__device__ int   g_bsum[256];

// ---------------- packed f32x2 helpers (FFMA2 path, PTX-only) ----------------
__device__ __forceinline__ unsigned long long pack2f(float w) {
    unsigned long long r;
    asm("mov.b64 %0, {%1, %1};" : "=l"(r) : "f"(w));
    return r;
}
__device__ __forceinline__ void fma2(unsigned long long& d,
                                     unsigned long long a, unsigned long long b) {
    asm("fma.rn.f32x2 %0, %1, %2, %3;" : "=l"(d) : "l"(a), "l"(b), "l"(d));
}
__device__ __forceinline__ float2 unpack2f(unsigned long long v) {
    float2 f;
    asm("mov.b64 {%0, %1}, %2;" : "=f"(f.x), "=f"(f.y) : "l"(v));
    return f;
}

#define ST 36   // padded row stride for transposed activation tiles (floats)

// ---------------- input projection: h0 = (relu(x@Wt+bt) ++ Et[type]) @ Wp + bp
// 32 nodes per block iteration; phase A computes the F->D relu GEMM into a
// transposed tile, phase B is a (D+TE)x D GEMM with packed f32x2 FMA.
__global__ void k_input_proj(const float* __restrict__ x,
                             const int* __restrict__ ntype,
                             const float* __restrict__ Wt, const float* __restrict__ bt,
                             const float* __restrict__ Et,
                             const float* __restrict__ Wp, const float* __restrict__ bp)
{
    __shared__ float sWt[FF * D];            // [f][j]
    __shared__ float sWp[(D + TEE) * D];     // [k][j]  20KB
    __shared__ float sbt[D], sbp[D];
    __shared__ float sEt[3 * TEE];
    __shared__ float sx[32 * FF];            // staged x rows
    __shared__ int   sty[32];
    __shared__ float shT[(D + TEE) * ST];    // transposed tile [k][node]

    int tid = threadIdx.x;
    for (int i = tid; i < FF * D; i += 256) sWt[i] = Wt[i];
    for (int i = tid; i < (D + TEE) * D; i += 256) sWp[i] = Wp[i];
    if (tid < D) { sbt[tid] = bt[tid]; sbp[tid] = bp[tid]; }
    if (tid < 3 * TEE) sEt[tid] = Et[tid];
    __syncthreads();

    int slot = tid >> 6;          // 0..3, 8 nodes each in phase B
    int j = tid & 63;
    unsigned long long bp2 = pack2f(sbp[j]);

    for (int n0 = blockIdx.x * 32; n0 < NN; n0 += gridDim.x * 32) {
        // stage x rows (32 nodes x 8 feats = 256 floats, fully coalesced)
        {
            int node = tid >> 3;
            sx[tid] = (n0 + node < NN) ? x[n0 * FF + tid] : 0.0f;
            if (tid < 32) sty[tid] = (n0 + tid < NN) ? ntype[n0 + tid] : 0;
        }
        __syncthreads();

        // phase A: relu(x @ Wt + bt) -> shT[j][node], thread = (node, 8 j's)
        {
            int node = tid >> 3;
            int jb = (tid & 7) * 8;
            float xv[FF];
            #pragma unroll
            for (int f = 0; f < FF; f++) xv[f] = sx[node * FF + f];
            #pragma unroll
            for (int jj = 0; jj < 8; jj++) {
                float acc = sbt[jb + jj];
                #pragma unroll
                for (int f = 0; f < FF; f++) acc += xv[f] * sWt[f * D + jb + jj];
                shT[(jb + jj) * ST + node] = fmaxf(acc, 0.0f);
            }
            // type embedding rows D..D+TE-1
            for (int i = tid; i < 32 * TEE; i += 256) {
                int nd = i >> 4, t = i & 15;
                shT[(D + t) * ST + nd] = sEt[sty[nd] * TEE + t];
            }
        }
        __syncthreads();

        // phase B: (D+TE) x D GEMM, 8 nodes per slot, packed pairs
        {
            unsigned long long a[4];
            #pragma unroll
            for (int p = 0; p < 4; p++) a[p] = bp2;
            #pragma unroll 4
            for (int k = 0; k < D + TEE; k++) {
                const ulonglong2* hp =
                    reinterpret_cast<const ulonglong2*>(&shT[k * ST + slot * 8]);
                ulonglong2 h01 = hp[0];
                ulonglong2 h23 = hp[1];
                unsigned long long w2 = pack2f(sWp[k * D + j]);
                fma2(a[0], h01.x, w2);
                fma2(a[1], h01.y, w2);
                fma2(a[2], h23.x, w2);
                fma2(a[3], h23.y, w2);
            }
            #pragma unroll
            for (int p = 0; p < 4; p++) {
                float2 f = unpack2f(a[p]);
                int n = n0 + slot * 8 + 2 * p;
                if (n < NN)     { g_h[n * D + j] = f.x;       g_h0[n * D + j] = f.x; }
                if (n + 1 < NN) { g_h[(n + 1) * D + j] = f.y; g_h0[(n + 1) * D + j] = f.y; }
            }
        }
        __syncthreads();
    }
}

// ---------------- CSR build by destination ----------------
__global__ void k_zero_deg()
{
    for (int i = blockIdx.x * blockDim.x + threadIdx.x; i < NN; i += gridDim.x * blockDim.x)
        g_deg[i] = 0;
}

__global__ void k_hist(const int* __restrict__ dst)
{
    for (int e = blockIdx.x * blockDim.x + threadIdx.x; e < ETOT; e += gridDim.x * blockDim.x) {
        int d = (e < EE) ? dst[e] : (e - EE);
        atomicAdd(&g_deg[d], 1);
    }
}

// --- parallel 3-phase scan: 256 blocks x 256 threads covers 65536 >= NN ---
__global__ void k_scan1()
{
    __shared__ int sh[256];
    int tid = threadIdx.x;
    int i = blockIdx.x * 256 + tid;
    int v = (i < NN) ? g_deg[i] : 0;
    sh[tid] = v;
    __syncthreads();
    int acc = v;
    #pragma unroll
    for (int off = 1; off < 256; off <<= 1) {
        int t = (tid >= off) ? sh[tid - off] : 0;
        __syncthreads();
        acc += t;
        sh[tid] = acc;
        __syncthreads();
    }
    if (i < NN) g_rowptr[i] = acc - v;
    if (tid == 255) g_bsum[blockIdx.x] = acc;
}

__global__ void k_scan2()
{
    __shared__ int sh[256];
    int tid = threadIdx.x;
    int v = g_bsum[tid];
    sh[tid] = v;
    __syncthreads();
    int acc = v;
    #pragma unroll
    for (int off = 1; off < 256; off <<= 1) {
        int t = (tid >= off) ? sh[tid - off] : 0;
        __syncthreads();
        acc += t;
        sh[tid] = acc;
        __syncthreads();
    }
    g_bsum[tid] = acc - v;
}

__global__ void k_scan3()
{
    int i = blockIdx.x * 256 + threadIdx.x;
    if (i < NN) {
        int r = g_rowptr[i] + g_bsum[blockIdx.x];
        g_rowptr[i] = r;
        g_cursor[i] = r;
    }
    if (i == 0) g_rowptr[NN] = ETOT;
}

__global__ void k_scatter(const int* __restrict__ src, const int* __restrict__ dst)
{
    for (int e = blockIdx.x * blockDim.x + threadIdx.x; e < ETOT; e += gridDim.x * blockDim.x) {
        int s, d;
        if (e < EE) { s = src[e]; d = dst[e]; }
        else        { s = d = e - EE; }
        int slot = atomicAdd(&g_cursor[d], 1);
        g_col[slot] = s;
    }
}

// ---------------- per-layer triple GEMM, packed-pair register blocking -------
// xl = h@Wl+bl, xr = h@Wr+br, xres = h@Wres+bconv
__global__ void k_gemm3(const float* __restrict__ Wl, const float* __restrict__ bl,
                        const float* __restrict__ Wr, const float* __restrict__ br,
                        const float* __restrict__ Wres, const float* __restrict__ bc,
                        int l)
{
    extern __shared__ float sm[];
    float* sA = sm;               // 4096
    float* sB = sm + 4096;        // 4096
    float* sC = sm + 8192;        // 4096
    float* shT = sm + 12288;      // [64][ST] transposed: shT[k][node]

    int tid = threadIdx.x;
    const float* Al = Wl + l * 4096;
    const float* Bl = Wr + l * 4096;
    const float* Cl = Wres + l * 4096;
    for (int i = tid; i < 4096; i += 256) {
        sA[i] = Al[i]; sB[i] = Bl[i]; sC[i] = Cl[i];
    }

    int slot = tid >> 6;          // 0..3, each handles 8 nodes
    int j = tid & 63;             // output column
    unsigned long long bL2 = pack2f(bl[l * D + j]);
    unsigned long long bR2 = pack2f(br[l * D + j]);
    unsigned long long bS2 = pack2f(bc[l * D + j]);
    __syncthreads();

    for (int n0 = blockIdx.x * 32; n0 < NN; n0 += gridDim.x * 32) {
        // load 32 nodes' h, transposed: shT[k][node]
        #pragma unroll
        for (int i = 0; i < 8; i++) {
            int node = slot * 8 + i;
            int n = n0 + node;
            shT[j * ST + node] = (n < NN) ? g_h[n * D + j] : 0.0f;
        }
        __syncthreads();

        unsigned long long aL[4], aR[4], aS[4];
        #pragma unroll
        for (int p = 0; p < 4; p++) { aL[p] = bL2; aR[p] = bR2; aS[p] = bS2; }

        #pragma unroll 4
        for (int k = 0; k < D; k++) {
            const ulonglong2* hp =
                reinterpret_cast<const ulonglong2*>(&shT[k * ST + slot * 8]);
            ulonglong2 h01 = hp[0];
            ulonglong2 h23 = hp[1];
            unsigned long long wl2 = pack2f(sA[k * D + j]);
            unsigned long long wr2 = pack2f(sB[k * D + j]);
            unsigned long long ws2 = pack2f(sC[k * D + j]);
            fma2(aL[0], h01.x, wl2); fma2(aL[1], h01.y, wl2);
            fma2(aL[2], h23.x, wl2); fma2(aL[3], h23.y, wl2);
            fma2(aR[0], h01.x, wr2); fma2(aR[1], h01.y, wr2);
            fma2(aR[2], h23.x, wr2); fma2(aR[3], h23.y, wr2);
            fma2(aS[0], h01.x, ws2); fma2(aS[1], h01.y, ws2);
            fma2(aS[2], h23.x, ws2); fma2(aS[3], h23.y, ws2);
        }

        #pragma unroll
        for (int p = 0; p < 4; p++) {
            float2 fL = unpack2f(aL[p]);
            float2 fR = unpack2f(aR[p]);
            float2 fS = unpack2f(aS[p]);
            int n = n0 + slot * 8 + 2 * p;
            if (n < NN) {
                g_xl[n * D + j] = fL.x;
                g_xr[n * D + j] = fR.x;
                g_xres[n * D + j] = fS.x;
            }
            if (n + 1 < NN) {
                g_xl[(n + 1) * D + j] = fL.y;
                g_xr[(n + 1) * D + j] = fR.y;
                g_xres[(n + 1) * D + j] = fS.y;
            }
        }
        __syncthreads();
    }
}

// ---------------- GAT layer: warp per node, single-sweep flash softmax, fused LN
__global__ void k_gat(const float* __restrict__ att,
                      const float* __restrict__ gamma, const float* __restrict__ beta,
                      const float* __restrict__ alpha_p, int l)
{
    int warp = threadIdx.x >> 5;
    int lane = threadIdx.x & 31;
    int n = blockIdx.x * (blockDim.x >> 5) + warp;
    if (n >= NN) return;

    int head = lane >> 3;            // lanes 8h..8h+7 cover head h
    int c0 = (2 * lane) & 15;
    float a0 = att[l * (HH * CC) + head * CC + c0];
    float a1 = att[l * (HH * CC) + head * CC + c0 + 1];

    float2 xr2 = *reinterpret_cast<const float2*>(&g_xr[n * D + 2 * lane]);
    int beg = g_rowptr[n];
    int end = g_rowptr[n + 1];

    // two independent flash-softmax chains (even/odd edges) for ILP
    float mA = -1e30f, sA = 0.0f, accA0 = 0.0f, accA1 = 0.0f;
    float mB = -1e30f, sB = 0.0f, accB0 = 0.0f, accB1 = 0.0f;

    for (int e = beg; e < end; e += 2) {
        int has1 = (e + 1 < end);
        int s0 = g_col[e];
        int s1 = has1 ? g_col[e + 1] : s0;
        float2 x0 = *reinterpret_cast<const float2*>(&g_xl[s0 * D + 2 * lane]);
        float2 x1 = *reinterpret_cast<const float2*>(&g_xl[s1 * D + 2 * lane]);

        {
            float v0 = x0.x + xr2.x; v0 = v0 > 0.0f ? v0 : 0.2f * v0;
            float v1 = x0.y + xr2.y; v1 = v1 > 0.0f ? v1 : 0.2f * v1;
            float p = a0 * v0 + a1 * v1;
            p += __shfl_xor_sync(0xffffffffu, p, 1);
            p += __shfl_xor_sync(0xffffffffu, p, 2);
            p += __shfl_xor_sync(0xffffffffu, p, 4);
            float nm = fmaxf(mA, p);
            float f = __expf(mA - nm);
            float w = __expf(p - nm);
            sA = sA * f + w;
            accA0 = accA0 * f + x0.x * w;
            accA1 = accA1 * f + x0.y * w;
            mA = nm;
        }
        if (has1) {
            float v0 = x1.x + xr2.x; v0 = v0 > 0.0f ? v0 : 0.2f * v0;
            float v1 = x1.y + xr2.y; v1 = v1 > 0.0f ? v1 : 0.2f * v1;
            float p = a0 * v0 + a1 * v1;
            p += __shfl_xor_sync(0xffffffffu, p, 1);
            p += __shfl_xor_sync(0xffffffffu, p, 2);
            p += __shfl_xor_sync(0xffffffffu, p, 4);
            float nm = fmaxf(mB, p);
            float f = __expf(mB - nm);
            float w = __expf(p - nm);
            sB = sB * f + w;
            accB0 = accB0 * f + x1.x * w;
            accB1 = accB1 * f + x1.y * w;
            mB = nm;
        }
    }

    // merge chains
    float m = fmaxf(mA, mB);
    float fA = __expf(mA - m);
    float fB = __expf(mB - m);
    float s = sA * fA + sB * fB;
    float acc0 = accA0 * fA + accB0 * fB;
    float acc1 = accA1 * fA + accB1 * fB;
    float inv_s = 1.0f / (s + 1e-16f);
    acc0 *= inv_s;
    acc1 *= inv_s;

    // epilogue: residual GEMM term + skip + LayerNorm, all in-warp
    float2 xres2 = *reinterpret_cast<const float2*>(&g_xres[n * D + 2 * lane]);
    float2 h02 = *reinterpret_cast<const float2*>(&g_h0[n * D + 2 * lane]);
    float al = *alpha_p;
    float v0 = al * (acc0 + xres2.x) + (1.0f - al) * h02.x;
    float v1 = al * (acc1 + xres2.y) + (1.0f - al) * h02.y;

    float sum = v0 + v1;
    float sq = v0 * v0 + v1 * v1;
    #pragma unroll
    for (int off = 16; off >= 1; off >>= 1) {
        sum += __shfl_xor_sync(0xffffffffu, sum, off);
        sq  += __shfl_xor_sync(0xffffffffu, sq, off);
    }
    float mu = sum * (1.0f / D);
    float var = sq * (1.0f / D) - mu * mu;
    float inv = rsqrtf(var + 1e-5f);

    float g0 = gamma[l * D + 2 * lane], g1 = gamma[l * D + 2 * lane + 1];
    float b0 = beta[l * D + 2 * lane],  b1 = beta[l * D + 2 * lane + 1];
    float2 outv;
    outv.x = g0 * (v0 - mu) * inv + b0;
    outv.y = g1 * (v1 - mu) * inv + b1;
    *reinterpret_cast<float2*>(&g_h[n * D + 2 * lane]) = outv;
}

// ---------------- output head: sigmoid(relu(h@W1+b1)@W2+b2) ----------------
__global__ void k_head(const float* __restrict__ W1, const float* __restrict__ b1,
                       const float* __restrict__ W2, const float* __restrict__ b2,
                       float* __restrict__ out)
{
    __shared__ float sW1[D * 32];
    __shared__ float sW2[32];
    __shared__ float sb1[32];
    int tid = threadIdx.x;
    for (int i = tid; i < D * 32; i += 256) sW1[i] = W1[i];
    if (tid < 32) { sW2[tid] = W2[tid]; sb1[tid] = b1[tid]; }
    __syncthreads();

    int warp = tid >> 5;
    int lane = tid & 31;
    float b2v = b2[0];
    for (int n = blockIdx.x * 8 + warp; n < NN; n += gridDim.x * 8) {
        float acc = sb1[lane];
        const float* hr = &g_h[n * D];
        #pragma unroll 16
        for (int k = 0; k < D; k++) acc += hr[k] * sW1[k * 32 + lane];
        float z = fmaxf(acc, 0.0f);
        float p = z * sW2[lane];
        #pragma unroll
        for (int off = 16; off >= 1; off >>= 1)
            p += __shfl_xor_sync(0xffffffffu, p, off);
        if (lane == 0) out[n] = 1.0f / (1.0f + __expf(-(p + b2v)));
    }
}

// ---------------- launch ----------------
extern "C" void kernel_launch(void* const* d_in, const int* in_sizes, int n_in,
                              void* d_out, int out_size)
{
    const float* x        = (const float*)d_in[0];
    const int*   ntype    = (const int*)d_in[1];
    const int*   esrc     = (const int*)d_in[2];
    const int*   edst     = (const int*)d_in[3];
    const float* Wt       = (const float*)d_in[4];
    const float* bt       = (const float*)d_in[5];
    const float* Et       = (const float*)d_in[6];
    const float* Wp       = (const float*)d_in[7];
    const float* bp       = (const float*)d_in[8];
    const float* Wl       = (const float*)d_in[9];
    const float* bl       = (const float*)d_in[10];
    const float* Wr       = (const float*)d_in[11];
    const float* br       = (const float*)d_in[12];
    const float* att      = (const float*)d_in[13];
    const float* Wres     = (const float*)d_in[14];
    const float* bconv    = (const float*)d_in[15];
    const float* gamma    = (const float*)d_in[16];
    const float* beta     = (const float*)d_in[17];
    const float* alpha    = (const float*)d_in[18];
    const float* W1       = (const float*)d_in[19];
    const float* b1       = (const float*)d_in[20];
    const float* W2       = (const float*)d_in[21];
    const float* b2       = (const float*)d_in[22];
    float* out = (float*)d_out;

    // one-time resource setup (idempotent; does not change per-call work)
    static bool init_done = false;
    static cudaStream_t s1;
    static cudaEvent_t ev_fork, ev_csr;
    const int gemm3_smem = (3 * 4096 + 64 * ST) * sizeof(float);
    if (!init_done) {
        cudaFuncSetAttribute(k_gemm3, cudaFuncAttributeMaxDynamicSharedMemorySize, gemm3_smem);
        cudaStreamCreateWithFlags(&s1, cudaStreamNonBlocking);
        cudaEventCreateWithFlags(&ev_fork, cudaEventDisableTiming);
        cudaEventCreateWithFlags(&ev_csr, cudaEventDisableTiming);
        init_done = true;
    }

    // fork: CSR build on side stream, overlapping input projection + layer-0 GEMM
    cudaEventRecord(ev_fork, 0);
    cudaStreamWaitEvent(s1, ev_fork, 0);
    k_zero_deg<<<64, 256, 0, s1>>>();
    k_hist<<<1024, 256, 0, s1>>>(edst);
    k_scan1<<<256, 256, 0, s1>>>();
    k_scan2<<<1, 256, 0, s1>>>();
    k_scan3<<<256, 256, 0, s1>>>();
    k_scatter<<<1024, 256, 0, s1>>>(esrc, edst);
    cudaEventRecord(ev_csr, s1);

    // main stream: input projection then layer-0 transforms (no CSR dependency)
    k_input_proj<<<444, 256>>>(x, ntype, Wt, bt, Et, Wp, bp);
    k_gemm3<<<444, 256, gemm3_smem>>>(Wl, bl, Wr, br, Wres, bconv, 0);

    // join: attention needs the CSR
    cudaStreamWaitEvent(0, ev_csr, 0);
    k_gat<<<(NN + 7) / 8, 256>>>(att, gamma, beta, alpha, 0);
    for (int l = 1; l < LL; l++) {
        k_gemm3<<<444, 256, gemm3_smem>>>(Wl, bl, Wr, br, Wres, bconv, l);
        k_gat<<<(NN + 7) / 8, 256>>>(att, gamma, beta, alpha, l);
    }

    // output head
    k_head<<<(NN + 7) / 8, 256>>>(W1, b1, W2, b2, out);
}